// round 11
// baseline (speedup 1.0000x reference)
#include <cuda_runtime.h>

#define H        2048
#define H4       512
#define FOURH    8192
#define LIN      92
#define NH       13
#define MAXO     9
#define NOUT     27
#define GRID     512
#define TPB      256
#define OUT_C0   4096
#define OUT_H1   2048
#define OUT_C1   6144
#define OUT_HEAD 8192

// L2 keep-set: first KEEPB blocks of each matrix's block-range load with
// evict-normal (persist in L2 across graph replays); the rest use __ldcs.
// Keep bytes ~= (112/256)*67MB*2 + (224/512)*67MB + Wih0(3MB) + W1(6.8MB) ~= 98MB
#define KEEPB_A  112
#define KEEPB_B  224

__device__ float g_gates0[FOURH];
__device__ float g_gates1[FOURH];
__device__ float g_hid[NH * 64];
__device__ __align__(128) unsigned g_bar0;
__device__ __align__(128) unsigned g_bar1;
__device__ __align__(128) unsigned g_done;

__constant__ int c_pair_k[NOUT] = {0,0,0,0,0, 1,2,3,4,5,6,7,
                                   8,8,8,8,8,8,8,8,8, 9, 10,10,10, 11, 12};
__constant__ int c_pair_p[NOUT] = {0,1,2,3,4, 0,0,0,0,0,0,0,
                                   0,1,2,3,4,5,6,7,8, 0, 0,1,2, 0, 0};

__device__ __forceinline__ float sigf(float x) {
    return __fdividef(1.0f, 1.0f + __expf(-x));
}
__device__ __forceinline__ float tanh_fast(float x) {
    return 1.0f - __fdividef(2.0f, __expf(2.0f * x) + 1.0f);
}
__device__ __forceinline__ float warp_red(float v) {
    #pragma unroll
    for (int off = 16; off; off >>= 1) v += __shfl_down_sync(0xffffffffu, v, off);
    return v;
}
__device__ __forceinline__ float dot4(float4 a, float4 b) {
    return a.x * b.x + a.y * b.y + a.z * b.z + a.w * b.w;
}

template<bool KEEP>
__device__ __forceinline__ float4 ldw(const float4* p) {
    return KEEP ? __ldg(p) : __ldcs(p);
}

// 4 consecutive rows of W (stride H) dotted against shv.
template<bool KEEP>
__device__ __forceinline__ void dotrows4(const float* W, int row0,
                                         const float4* shv, int lane, float* acc) {
    const float4* Wr = reinterpret_cast<const float4*>(W) + (size_t)row0 * H4;
    acc[0] = acc[1] = acc[2] = acc[3] = 0.f;
    #pragma unroll
    for (int it = 0; it < 16; ++it) {
        const int o = it * 32 + lane;
        float4 hv = shv[o];
        #pragma unroll
        for (int r = 0; r < 4; ++r) {
            float4 w = ldw<KEEP>(Wr + (size_t)r * H4 + o);
            acc[r] += dot4(w, hv);
        }
    }
}

template<bool KEEP>
__device__ __forceinline__ void dotrows2(const float* W, int row0,
                                         const float4* shv, int lane, float* acc) {
    const float4* Wr = reinterpret_cast<const float4*>(W) + (size_t)row0 * H4;
    acc[0] = acc[1] = 0.f;
    #pragma unroll
    for (int it = 0; it < 16; ++it) {
        const int o = it * 32 + lane;
        float4 hv = shv[o];
        #pragma unroll
        for (int r = 0; r < 2; ++r) {
            float4 w = ldw<KEEP>(Wr + (size_t)r * H4 + o);
            acc[r] += dot4(w, hv);
        }
    }
}

// Grid-wide barrier; all GRID blocks co-resident (launch_bounds(256,4):
// 4*148 = 592 >= 512). Last arriver resets the previous barrier's counter.
__device__ __forceinline__ void grid_bar(unsigned* cnt, unsigned* reset_prev) {
    __syncthreads();
    if (threadIdx.x == 0) {
        __threadfence();
        unsigned tok = atomicAdd(cnt, 1u);
        if (tok == GRID - 1 && reset_prev)
            *(volatile unsigned*)reset_prev = 0u;
        while (*(volatile unsigned*)cnt < (unsigned)GRID) __nanosleep(32);
        __threadfence();
    }
    __syncthreads();
}

// ---------------------------------------------------------------------------
__global__ void __launch_bounds__(TPB, 4)
k_all(const float* __restrict__ lap, const int* __restrict__ idx,
      const float* __restrict__ h_s, const float* __restrict__ c_s,
      const float* __restrict__ emb_team, const float* __restrict__ emb_track,
      const float* __restrict__ emb_driver, const float* __restrict__ emb_comp,
      const float* __restrict__ Wih0, const float* __restrict__ Whh0,
      const float* __restrict__ bih0, const float* __restrict__ bhh0,
      const float* __restrict__ Wih1, const float* __restrict__ Whh1,
      const float* __restrict__ bih1, const float* __restrict__ bhh1,
      const float* __restrict__ ln_g, const float* __restrict__ ln_b,
      const float* __restrict__ W1,  const float* __restrict__ b1,
      const float* __restrict__ W2,  const float* __restrict__ b2,
      float* __restrict__ out)
{
    __shared__ __align__(16) float sh[H];     // A: h_prev ; B: h0 ; C: ln(h1)
    __shared__ __align__(16) float sh_x[96];
    __shared__ float red_s[8], red_q[8];
    __shared__ unsigned s_tok;

    const int tid  = threadIdx.x;
    const int warp = tid >> 5, lane = tid & 31;
    const int b    = blockIdx.x;
    float4* sh4w = reinterpret_cast<float4*>(sh);
    const float4* sh4 = reinterpret_cast<const float4*>(sh);

    // ======================= Phase A ======================================
    // blocks 0..255: gates0 rows (Whh0 + Wih0); 256..511: gates1 (Whh1).
    {
        const bool part1 = (b >= 256);
        const int  lb    = b & 255;
        const float* hvec = part1 ? (h_s + H) : h_s;
        sh4w[tid]       = reinterpret_cast<const float4*>(hvec)[tid];
        sh4w[tid + 256] = reinterpret_cast<const float4*>(hvec)[tid + 256];
        if (!part1 && tid < LIN) {
            float v;
            if      (tid < 60) v = lap[tid];
            else if (tid < 68) v = emb_team  [idx[3] * 8 + (tid - 60)];
            else if (tid < 76) v = emb_track [idx[2] * 8 + (tid - 68)];
            else if (tid < 84) v = emb_driver[idx[1] * 8 + (tid - 76)];
            else               v = emb_comp  [idx[0] * 8 + (tid - 84)];
            sh_x[tid] = v;
        }
        __syncthreads();

        const int rowbase = lb * 32 + warp * 4;
        const float* W = part1 ? Whh1 : Whh0;
        float acc[4];
        if (lb < KEEPB_A) dotrows4<true >(W, rowbase, sh4, lane, acc);
        else              dotrows4<false>(W, rowbase, sh4, lane, acc);

        if (!part1 && lane < LIN / 4) {   // x contribution (23 float4/row)
            float4 xv = reinterpret_cast<const float4*>(sh_x)[lane];
            #pragma unroll
            for (int r = 0; r < 4; ++r) {
                float4 w = __ldg(reinterpret_cast<const float4*>(
                                     Wih0 + (size_t)(rowbase + r) * LIN) + lane);
                acc[r] += dot4(w, xv);
            }
        }
        #pragma unroll
        for (int r = 0; r < 4; ++r) acc[r] = warp_red(acc[r]);
        if (lane == 0) {
            #pragma unroll
            for (int r = 0; r < 4; ++r) {
                const int row = rowbase + r;
                if (!part1) g_gates0[row] = acc[r] + bih0[row] + bhh0[row];
                else        g_gates1[row] = acc[r] + bih1[row] + bhh1[row];
            }
        }
    }
    grid_bar(&g_bar0, nullptr);

    // ======== Phase B: h0/c0 recompute + gates1 += Wih1 @ h0 ==============
    {
        #pragma unroll
        for (int t = 0; t < 8; ++t) {
            const int j = tid + t * 256;
            float i  = sigf(g_gates0[j]);
            float f  = sigf(g_gates0[H + j]);
            float gg = tanh_fast(g_gates0[2 * H + j]);
            float o  = sigf(g_gates0[3 * H + j]);
            float cc = f * c_s[j] + i * gg;
            float hh = o * tanh_fast(cc);
            sh[j] = hh;
            if (b == 0) { out[OUT_C0 + j] = cc; out[j] = hh; }
        }
        __syncthreads();

        const int rowbase = b * 16 + warp * 2;
        float acc[2];
        if (b < KEEPB_B) dotrows2<true >(Wih1, rowbase, sh4, lane, acc);
        else             dotrows2<false>(Wih1, rowbase, sh4, lane, acc);
        acc[0] = warp_red(acc[0]);
        acc[1] = warp_red(acc[1]);
        if (lane == 0) {
            g_gates1[rowbase]     += acc[0];
            g_gates1[rowbase + 1] += acc[1];
        }
    }
    grid_bar(&g_bar1, &g_bar0);

    // ======== Phase C: h1/c1 + LN recompute + head W1 (blocks 0..103) =====
    if (b < 104) {
        const float* c_prev = c_s + H;
        float s = 0.f, q = 0.f;
        #pragma unroll
        for (int t = 0; t < 8; ++t) {
            const int j = tid + t * 256;
            float i  = sigf(g_gates1[j]);
            float f  = sigf(g_gates1[H + j]);
            float gg = tanh_fast(g_gates1[2 * H + j]);
            float o  = sigf(g_gates1[3 * H + j]);
            float cc = f * c_prev[j] + i * gg;
            float hh = o * tanh_fast(cc);
            if (b == 0) { out[OUT_C1 + j] = cc; out[OUT_H1 + j] = hh; }
            sh[j] = hh;
            s += hh;
            q += hh * hh;
        }
        s = warp_red(s); q = warp_red(q);
        if (lane == 0) { red_s[warp] = s; red_q[warp] = q; }
        __syncthreads();
        if (tid == 0) {
            float ss = 0.f, qq = 0.f;
            #pragma unroll
            for (int w = 0; w < 8; ++w) { ss += red_s[w]; qq += red_q[w]; }
            red_s[0] = ss; red_q[0] = qq;
        }
        __syncthreads();
        const float mu   = red_s[0] * (1.0f / H);
        const float var  = red_q[0] * (1.0f / H) - mu * mu;
        const float rstd = rsqrtf(var + 1e-5f);
        #pragma unroll
        for (int t = 0; t < 8; ++t) {
            const int j = tid + t * 256;
            sh[j] = (sh[j] - mu) * rstd * ln_g[j] + ln_b[j];
        }
        __syncthreads();

        const int g = b * 8 + warp;        // 0..831 = NH*64 W1 rows
        const float4* W4 = reinterpret_cast<const float4*>(W1 + (size_t)g * H);
        float acc = 0.f;
        #pragma unroll
        for (int it = 0; it < 16; ++it) {
            float4 w  = __ldg(W4 + it * 32 + lane);
            float4 hv = sh4[it * 32 + lane];
            acc += dot4(w, hv);
        }
        acc = warp_red(acc);
        if (lane == 0)
            g_hid[g] = fmaxf(acc + b1[g], 0.0f);
    }

    // ============ completion; last block computes W2 + resets =============
    __syncthreads();
    if (tid == 0) { __threadfence(); s_tok = atomicAdd(&g_done, 1u); }
    __syncthreads();

    if (s_tok == GRID - 1) {
        __threadfence();
        for (int j = warp; j < NOUT; j += 8) {
            const int k = c_pair_k[j], p = c_pair_p[j];
            const float* hid = g_hid + k * 64;
            const float* w2  = W2 + ((size_t)k * MAXO + p) * 64;
            float acc = hid[lane] * w2[lane] + hid[lane + 32] * w2[lane + 32];
            acc = warp_red(acc);
            if (lane == 0)
                out[OUT_HEAD + j] = acc + b2[k * MAXO + p];
        }
        __syncthreads();
        if (tid == 0) {               // clean state for next graph replay
            *(volatile unsigned*)&g_bar1 = 0u;
            *(volatile unsigned*)&g_done = 0u;
            __threadfence();
        }
    }
}

// ---------------------------------------------------------------------------
extern "C" void kernel_launch(void* const* d_in, const int* in_sizes, int n_in,
                              void* d_out, int out_size)
{
    const float* lap        = (const float*)d_in[0];
    const int*   idx        = (const int*)  d_in[1];
    const float* h_s        = (const float*)d_in[2];
    const float* c_s        = (const float*)d_in[3];
    const float* emb_team   = (const float*)d_in[4];
    const float* emb_track  = (const float*)d_in[5];
    const float* emb_driver = (const float*)d_in[6];
    const float* emb_comp   = (const float*)d_in[7];
    const float* Wih0       = (const float*)d_in[8];
    const float* Whh0       = (const float*)d_in[9];
    const float* bih0       = (const float*)d_in[10];
    const float* bhh0       = (const float*)d_in[11];
    const float* Wih1       = (const float*)d_in[12];
    const float* Whh1       = (const float*)d_in[13];
    const float* bih1       = (const float*)d_in[14];
    const float* bhh1       = (const float*)d_in[15];
    const float* ln_g       = (const float*)d_in[16];
    const float* ln_b       = (const float*)d_in[17];
    const float* hW1        = (const float*)d_in[18];
    const float* hb1        = (const float*)d_in[19];
    const float* hW2        = (const float*)d_in[20];
    const float* hb2        = (const float*)d_in[21];
    float* out = (float*)d_out;

    k_all<<<GRID, TPB>>>(lap, idx, h_s, c_s, emb_team, emb_track, emb_driver,
                         emb_comp, Wih0, Whh0, bih0, bhh0, Wih1, Whh1, bih1,
                         bhh1, ln_g, ln_b, hW1, hb1, hW2, hb2, out);
}

// round 12
// speedup vs baseline: 1.0359x; 1.0359x over previous
#include <cuda_runtime.h>

#define H        2048
#define H4       512
#define FOURH    8192
#define LIN      92
#define NH       13
#define MAXO     9
#define NOUT     27
#define GRID     512
#define TPB      256
#define OUT_C0   4096
#define OUT_H1   2048
#define OUT_C1   6144
#define OUT_HEAD 8192

// L2 keep-set: first KEEPB blocks of each matrix's block-range load with
// evict-normal (persist in L2 across graph replays); the rest use __ldcs.
// Keep bytes ~= (112/256)*67MB*2 + (224/512)*67MB + Wih0(3MB) + W1(6.8MB) ~= 98MB
#define KEEPB_A  112
#define KEEPB_B  224

__device__ float g_gates0[FOURH];
__device__ float g_gates1[FOURH];
__device__ float g_hid[NH * 64];
__device__ __align__(128) unsigned g_bar0;
__device__ __align__(128) unsigned g_bar1;
__device__ __align__(128) unsigned g_done;

__constant__ int c_pair_k[NOUT] = {0,0,0,0,0, 1,2,3,4,5,6,7,
                                   8,8,8,8,8,8,8,8,8, 9, 10,10,10, 11, 12};
__constant__ int c_pair_p[NOUT] = {0,1,2,3,4, 0,0,0,0,0,0,0,
                                   0,1,2,3,4,5,6,7,8, 0, 0,1,2, 0, 0};

__device__ __forceinline__ float sigf(float x) {
    return __fdividef(1.0f, 1.0f + __expf(-x));
}
__device__ __forceinline__ float tanh_fast(float x) {
    return 1.0f - __fdividef(2.0f, __expf(2.0f * x) + 1.0f);
}
__device__ __forceinline__ float warp_red(float v) {
    #pragma unroll
    for (int off = 16; off; off >>= 1) v += __shfl_down_sync(0xffffffffu, v, off);
    return v;
}
__device__ __forceinline__ float dot4(float4 a, float4 b) {
    return a.x * b.x + a.y * b.y + a.z * b.z + a.w * b.w;
}

template<bool KEEP>
__device__ __forceinline__ float4 ldw(const float4* p) {
    return KEEP ? __ldg(p) : __ldcs(p);
}

// 4 consecutive rows of W (stride H) dotted against shv.
template<bool KEEP>
__device__ __forceinline__ void dotrows4(const float* W, int row0,
                                         const float4* shv, int lane, float* acc) {
    const float4* Wr = reinterpret_cast<const float4*>(W) + (size_t)row0 * H4;
    acc[0] = acc[1] = acc[2] = acc[3] = 0.f;
    #pragma unroll
    for (int it = 0; it < 16; ++it) {
        const int o = it * 32 + lane;
        float4 hv = shv[o];
        #pragma unroll
        for (int r = 0; r < 4; ++r) {
            float4 w = ldw<KEEP>(Wr + (size_t)r * H4 + o);
            acc[r] += dot4(w, hv);
        }
    }
}

template<bool KEEP>
__device__ __forceinline__ void dotrows2(const float* W, int row0,
                                         const float4* shv, int lane, float* acc) {
    const float4* Wr = reinterpret_cast<const float4*>(W) + (size_t)row0 * H4;
    acc[0] = acc[1] = 0.f;
    #pragma unroll
    for (int it = 0; it < 16; ++it) {
        const int o = it * 32 + lane;
        float4 hv = shv[o];
        #pragma unroll
        for (int r = 0; r < 2; ++r) {
            float4 w = ldw<KEEP>(Wr + (size_t)r * H4 + o);
            acc[r] += dot4(w, hv);
        }
    }
}

// Grid-wide barrier; all GRID blocks co-resident (launch_bounds(256,4):
// 4*148 = 592 >= 512). Last arriver resets the previous barrier's counter.
__device__ __forceinline__ void grid_bar(unsigned* cnt, unsigned* reset_prev) {
    __syncthreads();
    if (threadIdx.x == 0) {
        __threadfence();
        unsigned tok = atomicAdd(cnt, 1u);
        if (tok == GRID - 1 && reset_prev)
            *(volatile unsigned*)reset_prev = 0u;
        while (*(volatile unsigned*)cnt < (unsigned)GRID) __nanosleep(32);
        __threadfence();
    }
    __syncthreads();
}

// ---------------------------------------------------------------------------
__global__ void __launch_bounds__(TPB, 4)
k_all(const float* __restrict__ lap, const int* __restrict__ idx,
      const float* __restrict__ h_s, const float* __restrict__ c_s,
      const float* __restrict__ emb_team, const float* __restrict__ emb_track,
      const float* __restrict__ emb_driver, const float* __restrict__ emb_comp,
      const float* __restrict__ Wih0, const float* __restrict__ Whh0,
      const float* __restrict__ bih0, const float* __restrict__ bhh0,
      const float* __restrict__ Wih1, const float* __restrict__ Whh1,
      const float* __restrict__ bih1, const float* __restrict__ bhh1,
      const float* __restrict__ ln_g, const float* __restrict__ ln_b,
      const float* __restrict__ W1,  const float* __restrict__ b1,
      const float* __restrict__ W2,  const float* __restrict__ b2,
      float* __restrict__ out)
{
    __shared__ __align__(16) float sh[H];     // A: h_prev ; B: h0 ; C: ln(h1)
    __shared__ __align__(16) float sh_x[96];
    __shared__ float red_s[8], red_q[8];
    __shared__ unsigned s_tok;

    const int tid  = threadIdx.x;
    const int warp = tid >> 5, lane = tid & 31;
    const int b    = blockIdx.x;
    float4* sh4w = reinterpret_cast<float4*>(sh);
    const float4* sh4 = reinterpret_cast<const float4*>(sh);

    // ======================= Phase A ======================================
    // blocks 0..255: gates0 rows (Whh0 + Wih0); 256..511: gates1 (Whh1).
    {
        const bool part1 = (b >= 256);
        const int  lb    = b & 255;
        const float* hvec = part1 ? (h_s + H) : h_s;
        sh4w[tid]       = reinterpret_cast<const float4*>(hvec)[tid];
        sh4w[tid + 256] = reinterpret_cast<const float4*>(hvec)[tid + 256];
        if (!part1 && tid < LIN) {
            float v;
            if      (tid < 60) v = lap[tid];
            else if (tid < 68) v = emb_team  [idx[3] * 8 + (tid - 60)];
            else if (tid < 76) v = emb_track [idx[2] * 8 + (tid - 68)];
            else if (tid < 84) v = emb_driver[idx[1] * 8 + (tid - 76)];
            else               v = emb_comp  [idx[0] * 8 + (tid - 84)];
            sh_x[tid] = v;
        }
        __syncthreads();

        const int rowbase = lb * 32 + warp * 4;
        const float* W = part1 ? Whh1 : Whh0;
        float acc[4];
        if (lb < KEEPB_A) dotrows4<true >(W, rowbase, sh4, lane, acc);
        else              dotrows4<false>(W, rowbase, sh4, lane, acc);

        if (!part1 && lane < LIN / 4) {   // x contribution (23 float4/row)
            float4 xv = reinterpret_cast<const float4*>(sh_x)[lane];
            #pragma unroll
            for (int r = 0; r < 4; ++r) {
                float4 w = __ldg(reinterpret_cast<const float4*>(
                                     Wih0 + (size_t)(rowbase + r) * LIN) + lane);
                acc[r] += dot4(w, xv);
            }
        }
        #pragma unroll
        for (int r = 0; r < 4; ++r) acc[r] = warp_red(acc[r]);
        if (lane == 0) {
            #pragma unroll
            for (int r = 0; r < 4; ++r) {
                const int row = rowbase + r;
                if (!part1) g_gates0[row] = acc[r] + bih0[row] + bhh0[row];
                else        g_gates1[row] = acc[r] + bih1[row] + bhh1[row];
            }
        }
    }
    grid_bar(&g_bar0, nullptr);

    // ======== Phase B: h0/c0 recompute + gates1 += Wih1 @ h0 ==============
    {
        #pragma unroll
        for (int t = 0; t < 8; ++t) {
            const int j = tid + t * 256;
            float i  = sigf(g_gates0[j]);
            float f  = sigf(g_gates0[H + j]);
            float gg = tanh_fast(g_gates0[2 * H + j]);
            float o  = sigf(g_gates0[3 * H + j]);
            float cc = f * c_s[j] + i * gg;
            float hh = o * tanh_fast(cc);
            sh[j] = hh;
            if (b == 0) { out[OUT_C0 + j] = cc; out[j] = hh; }
        }
        __syncthreads();

        const int rowbase = b * 16 + warp * 2;
        float acc[2];
        if (b < KEEPB_B) dotrows2<true >(Wih1, rowbase, sh4, lane, acc);
        else             dotrows2<false>(Wih1, rowbase, sh4, lane, acc);
        acc[0] = warp_red(acc[0]);
        acc[1] = warp_red(acc[1]);
        if (lane == 0) {
            g_gates1[rowbase]     += acc[0];
            g_gates1[rowbase + 1] += acc[1];
        }
    }
    grid_bar(&g_bar1, &g_bar0);

    // ======== Phase C: h1/c1 + LN recompute + head W1 (blocks 0..103) =====
    if (b < 104) {
        const float* c_prev = c_s + H;
        float s = 0.f, q = 0.f;
        #pragma unroll
        for (int t = 0; t < 8; ++t) {
            const int j = tid + t * 256;
            float i  = sigf(g_gates1[j]);
            float f  = sigf(g_gates1[H + j]);
            float gg = tanh_fast(g_gates1[2 * H + j]);
            float o  = sigf(g_gates1[3 * H + j]);
            float cc = f * c_prev[j] + i * gg;
            float hh = o * tanh_fast(cc);
            if (b == 0) { out[OUT_C1 + j] = cc; out[OUT_H1 + j] = hh; }
            sh[j] = hh;
            s += hh;
            q += hh * hh;
        }
        s = warp_red(s); q = warp_red(q);
        if (lane == 0) { red_s[warp] = s; red_q[warp] = q; }
        __syncthreads();
        if (tid == 0) {
            float ss = 0.f, qq = 0.f;
            #pragma unroll
            for (int w = 0; w < 8; ++w) { ss += red_s[w]; qq += red_q[w]; }
            red_s[0] = ss; red_q[0] = qq;
        }
        __syncthreads();
        const float mu   = red_s[0] * (1.0f / H);
        const float var  = red_q[0] * (1.0f / H) - mu * mu;
        const float rstd = rsqrtf(var + 1e-5f);
        #pragma unroll
        for (int t = 0; t < 8; ++t) {
            const int j = tid + t * 256;
            sh[j] = (sh[j] - mu) * rstd * ln_g[j] + ln_b[j];
        }
        __syncthreads();

        const int g = b * 8 + warp;        // 0..831 = NH*64 W1 rows
        const float4* W4 = reinterpret_cast<const float4*>(W1 + (size_t)g * H);
        float acc = 0.f;
        #pragma unroll
        for (int it = 0; it < 16; ++it) {
            float4 w  = __ldg(W4 + it * 32 + lane);
            float4 hv = sh4[it * 32 + lane];
            acc += dot4(w, hv);
        }
        acc = warp_red(acc);
        if (lane == 0)
            g_hid[g] = fmaxf(acc + b1[g], 0.0f);
    }

    // ============ completion; last block computes W2 + resets =============
    __syncthreads();
    if (tid == 0) { __threadfence(); s_tok = atomicAdd(&g_done, 1u); }
    __syncthreads();

    if (s_tok == GRID - 1) {
        __threadfence();
        for (int j = warp; j < NOUT; j += 8) {
            const int k = c_pair_k[j], p = c_pair_p[j];
            const float* hid = g_hid + k * 64;
            const float* w2  = W2 + ((size_t)k * MAXO + p) * 64;
            float acc = hid[lane] * w2[lane] + hid[lane + 32] * w2[lane + 32];
            acc = warp_red(acc);
            if (lane == 0)
                out[OUT_HEAD + j] = acc + b2[k * MAXO + p];
        }
        __syncthreads();
        if (tid == 0) {               // clean state for next graph replay
            *(volatile unsigned*)&g_bar1 = 0u;
            *(volatile unsigned*)&g_done = 0u;
            __threadfence();
        }
    }
}

// ---------------------------------------------------------------------------
extern "C" void kernel_launch(void* const* d_in, const int* in_sizes, int n_in,
                              void* d_out, int out_size)
{
    const float* lap        = (const float*)d_in[0];
    const int*   idx        = (const int*)  d_in[1];
    const float* h_s        = (const float*)d_in[2];
    const float* c_s        = (const float*)d_in[3];
    const float* emb_team   = (const float*)d_in[4];
    const float* emb_track  = (const float*)d_in[5];
    const float* emb_driver = (const float*)d_in[6];
    const float* emb_comp   = (const float*)d_in[7];
    const float* Wih0       = (const float*)d_in[8];
    const float* Whh0       = (const float*)d_in[9];
    const float* bih0       = (const float*)d_in[10];
    const float* bhh0       = (const float*)d_in[11];
    const float* Wih1       = (const float*)d_in[12];
    const float* Whh1       = (const float*)d_in[13];
    const float* bih1       = (const float*)d_in[14];
    const float* bhh1       = (const float*)d_in[15];
    const float* ln_g       = (const float*)d_in[16];
    const float* ln_b       = (const float*)d_in[17];
    const float* hW1        = (const float*)d_in[18];
    const float* hb1        = (const float*)d_in[19];
    const float* hW2        = (const float*)d_in[20];
    const float* hb2        = (const float*)d_in[21];
    float* out = (float*)d_out;

    k_all<<<GRID, TPB>>>(lap, idx, h_s, c_s, emb_team, emb_track, emb_driver,
                         emb_comp, Wih0, Whh0, bih0, bhh0, Wih1, Whh1, bih1,
                         bhh1, ln_g, ln_b, hW1, hb1, hW2, hb2, out);
}

// round 13
// speedup vs baseline: 1.2927x; 1.2479x over previous
#include <cuda_runtime.h>

#define H        2048
#define H4       512
#define FOURH    8192
#define LIN      92
#define NH       13
#define MAXO     9
#define NOUT     27
#define GRID     512
#define TPB      256
#define OUT_C0   4096
#define OUT_H1   2048
#define OUT_C1   6144
#define OUT_HEAD 8192

// L2 keep-set (R7-proven 3/8 fraction, contiguous j-ranges per matrix):
#define KEEPA    96     // of 256 blocks per phase-A half
#define KEEPB    192    // of 512 blocks in phase B

__device__ float g_g1[FOURH];        // gates1 partial (Whh1 part + biases)
__device__ float g_h0[H];
__device__ float g_h1[H];
__device__ float g_ps[GRID];         // LN partial sums
__device__ float g_pq[GRID];         // LN partial sumsq
__device__ float g_hid[NH * 64];
__device__ __align__(128) unsigned g_bar0;
__device__ __align__(128) unsigned g_bar1;
__device__ __align__(128) unsigned g_done;

__constant__ int c_pair_k[NOUT] = {0,0,0,0,0, 1,2,3,4,5,6,7,
                                   8,8,8,8,8,8,8,8,8, 9, 10,10,10, 11, 12};
__constant__ int c_pair_p[NOUT] = {0,1,2,3,4, 0,0,0,0,0,0,0,
                                   0,1,2,3,4,5,6,7,8, 0, 0,1,2, 0, 0};

__device__ __forceinline__ float sigf(float x) {
    return __fdividef(1.0f, 1.0f + __expf(-x));
}
__device__ __forceinline__ float tanh_fast(float x) {
    return 1.0f - __fdividef(2.0f, __expf(2.0f * x) + 1.0f);
}
__device__ __forceinline__ float warp_red(float v) {
    #pragma unroll
    for (int off = 16; off; off >>= 1) v += __shfl_down_sync(0xffffffffu, v, off);
    return v;
}
__device__ __forceinline__ float dot4(float4 a, float4 b) {
    return a.x * b.x + a.y * b.y + a.z * b.z + a.w * b.w;
}

template<bool KEEP>
__device__ __forceinline__ float4 ldw(const float4* p) {
    return KEEP ? __ldg(p) : __ldcs(p);
}

// 4 gate rows {j, j+2048, j+4096, j+6144} of W dotted against shv.
template<bool KEEP>
__device__ __forceinline__ void gaterows4(const float* W, int j,
                                          const float4* shv, int lane, float* acc) {
    const float4* W0 = reinterpret_cast<const float4*>(W) + (size_t)j * H4;
    const float4* W1 = W0 + (size_t)2048 * H4;
    const float4* W2 = W1 + (size_t)2048 * H4;
    const float4* W3 = W2 + (size_t)2048 * H4;
    acc[0] = acc[1] = acc[2] = acc[3] = 0.f;
    #pragma unroll
    for (int it = 0; it < 16; ++it) {
        const int o = it * 32 + lane;
        float4 hv = shv[o];
        acc[0] += dot4(ldw<KEEP>(W0 + o), hv);
        acc[1] += dot4(ldw<KEEP>(W1 + o), hv);
        acc[2] += dot4(ldw<KEEP>(W2 + o), hv);
        acc[3] += dot4(ldw<KEEP>(W3 + o), hv);
    }
}

// 2 gate rows {j + 2048*r0, j + 2048*(r0+1)}
template<bool KEEP>
__device__ __forceinline__ void gaterows2(const float* W, int j, int r0,
                                          const float4* shv, int lane, float* acc) {
    const float4* W0 = reinterpret_cast<const float4*>(W) + ((size_t)j + 2048u * r0) * H4;
    const float4* W1 = W0 + (size_t)2048 * H4;
    acc[0] = acc[1] = 0.f;
    #pragma unroll
    for (int it = 0; it < 16; ++it) {
        const int o = it * 32 + lane;
        float4 hv = shv[o];
        acc[0] += dot4(ldw<KEEP>(W0 + o), hv);
        acc[1] += dot4(ldw<KEEP>(W1 + o), hv);
    }
}

// Grid barrier; all GRID blocks co-resident (launch_bounds(256,4): 4*148=592>=512)
__device__ __forceinline__ void grid_bar(unsigned* cnt, unsigned* reset_prev) {
    __syncthreads();
    if (threadIdx.x == 0) {
        __threadfence();
        unsigned tok = atomicAdd(cnt, 1u);
        if (tok == GRID - 1 && reset_prev)
            *(volatile unsigned*)reset_prev = 0u;
        while (*(volatile unsigned*)cnt < (unsigned)GRID) __nanosleep(32);
        __threadfence();
    }
    __syncthreads();
}

// ---------------------------------------------------------------------------
__global__ void __launch_bounds__(TPB, 4)
k_all(const float* __restrict__ lap, const int* __restrict__ idx,
      const float* __restrict__ h_s, const float* __restrict__ c_s,
      const float* __restrict__ emb_team, const float* __restrict__ emb_track,
      const float* __restrict__ emb_driver, const float* __restrict__ emb_comp,
      const float* __restrict__ Wih0, const float* __restrict__ Whh0,
      const float* __restrict__ bih0, const float* __restrict__ bhh0,
      const float* __restrict__ Wih1, const float* __restrict__ Whh1,
      const float* __restrict__ bih1, const float* __restrict__ bhh1,
      const float* __restrict__ ln_g, const float* __restrict__ ln_b,
      const float* __restrict__ W1,  const float* __restrict__ b1,
      const float* __restrict__ W2,  const float* __restrict__ b2,
      float* __restrict__ out)
{
    __shared__ __align__(16) float sh[H];
    __shared__ __align__(16) float sh_x[96];
    __shared__ float sred[16];        // phase B: 8 warps x 2 partials
    __shared__ float spart[4], sqart[4];
    __shared__ float red_s[8], red_q[8];
    __shared__ unsigned s_tok;

    const int tid  = threadIdx.x;
    const int warp = tid >> 5, lane = tid & 31;
    const int b    = blockIdx.x;
    float4* sh4w = reinterpret_cast<float4*>(sh);
    const float4* sh4 = reinterpret_cast<const float4*>(sh);

    // ======================= Phase A ======================================
    // blocks 0..255 : full layer-0 cell for 8 elements (gate-aligned rows)
    // blocks 256..511: Whh1 partial gates for 8 elements
    {
        const bool part1 = (b >= 256);
        const int  lb    = b & 255;
        const float* hvec = part1 ? (h_s + H) : h_s;
        sh4w[tid]       = reinterpret_cast<const float4*>(hvec)[tid];
        sh4w[tid + 256] = reinterpret_cast<const float4*>(hvec)[tid + 256];
        if (!part1 && tid < LIN) {
            float v;
            if      (tid < 60) v = lap[tid];
            else if (tid < 68) v = emb_team  [idx[3] * 8 + (tid - 60)];
            else if (tid < 76) v = emb_track [idx[2] * 8 + (tid - 68)];
            else if (tid < 84) v = emb_driver[idx[1] * 8 + (tid - 76)];
            else               v = emb_comp  [idx[0] * 8 + (tid - 84)];
            sh_x[tid] = v;
        }
        __syncthreads();

        const int j = lb * 8 + warp;              // element 0..2047
        const float* W = part1 ? Whh1 : Whh0;
        float acc[4];
        if (lb < KEEPA) gaterows4<true >(W, j, sh4, lane, acc);
        else            gaterows4<false>(W, j, sh4, lane, acc);

        if (!part1 && lane < LIN / 4) {           // Wih0 @ x, 4 gate rows
            float4 xv = reinterpret_cast<const float4*>(sh_x)[lane];
            #pragma unroll
            for (int r = 0; r < 4; ++r) {
                float4 w = __ldg(reinterpret_cast<const float4*>(
                                     Wih0 + (size_t)(j + 2048 * r) * LIN) + lane);
                acc[r] += dot4(w, xv);
            }
        }
        #pragma unroll
        for (int r = 0; r < 4; ++r) acc[r] = warp_red(acc[r]);

        if (lane == 0) {
            if (!part1) {                          // complete layer-0 cell
                float gi = acc[0] + __ldg(bih0 + j)        + __ldg(bhh0 + j);
                float gf = acc[1] + __ldg(bih0 + j + 2048) + __ldg(bhh0 + j + 2048);
                float gg = acc[2] + __ldg(bih0 + j + 4096) + __ldg(bhh0 + j + 4096);
                float go = acc[3] + __ldg(bih0 + j + 6144) + __ldg(bhh0 + j + 6144);
                float cc = sigf(gf) * __ldg(c_s + j) + sigf(gi) * tanh_fast(gg);
                float hh = sigf(go) * tanh_fast(cc);
                g_h0[j] = hh;
                out[j] = hh;
                out[OUT_C0 + j] = cc;
            } else {                               // gates1 partial + biases
                g_g1[j]        = acc[0] + __ldg(bih1 + j)        + __ldg(bhh1 + j);
                g_g1[j + 2048] = acc[1] + __ldg(bih1 + j + 2048) + __ldg(bhh1 + j + 2048);
                g_g1[j + 4096] = acc[2] + __ldg(bih1 + j + 4096) + __ldg(bhh1 + j + 4096);
                g_g1[j + 6144] = acc[3] + __ldg(bih1 + j + 6144) + __ldg(bhh1 + j + 6144);
            }
        }
    }
    grid_bar(&g_bar0, nullptr);

    // ======== Phase B: Wih1 @ h0 (paired warps per element) + cell ========
    {
        sh4w[tid]       = reinterpret_cast<const float4*>(g_h0)[tid];
        sh4w[tid + 256] = reinterpret_cast<const float4*>(g_h0)[tid + 256];
        __syncthreads();

        const int t  = warp >> 1;                 // 0..3: element slot
        const int pr = warp & 1;                  // 0: gates i,f ; 1: g,o
        const int j  = b * 4 + t;
        float acc[2];
        if (b < KEEPB) gaterows2<true >(Wih1, j, pr * 2, sh4, lane, acc);
        else           gaterows2<false>(Wih1, j, pr * 2, sh4, lane, acc);
        acc[0] = warp_red(acc[0]);
        acc[1] = warp_red(acc[1]);
        if (lane == 0) {
            sred[t * 4 + pr * 2]     = acc[0];
            sred[t * 4 + pr * 2 + 1] = acc[1];
        }
        __syncthreads();

        if (tid < 4) {                            // complete layer-1 cell
            const int jj = b * 4 + tid;
            float gi = sred[tid * 4]     + g_g1[jj];
            float gf = sred[tid * 4 + 1] + g_g1[jj + 2048];
            float gg = sred[tid * 4 + 2] + g_g1[jj + 4096];
            float go = sred[tid * 4 + 3] + g_g1[jj + 6144];
            float cc = sigf(gf) * __ldg(c_s + H + jj) + sigf(gi) * tanh_fast(gg);
            float hh = sigf(go) * tanh_fast(cc);
            g_h1[jj] = hh;
            out[OUT_C1 + jj] = cc;
            out[OUT_H1 + jj] = hh;
            spart[tid] = hh;
            sqart[tid] = hh * hh;
        }
        __syncthreads();
        if (tid == 0) {
            g_ps[b] = spart[0] + spart[1] + spart[2] + spart[3];
            g_pq[b] = sqart[0] + sqart[1] + sqart[2] + sqart[3];
        }
    }
    grid_bar(&g_bar1, &g_bar0);

    // ======== Phase C: LN + head W1 (blocks 0..103) =======================
    if (b < 104) {
        // deterministic fixed-tree reduction of 512 partials
        float s = g_ps[tid] + g_ps[tid + 256];
        float q = g_pq[tid] + g_pq[tid + 256];
        s = warp_red(s); q = warp_red(q);
        if (lane == 0) { red_s[warp] = s; red_q[warp] = q; }
        __syncthreads();
        if (tid == 0) {
            float ss = 0.f, qq = 0.f;
            #pragma unroll
            for (int w = 0; w < 8; ++w) { ss += red_s[w]; qq += red_q[w]; }
            const float mu  = ss * (1.0f / H);
            const float var = qq * (1.0f / H) - mu * mu;
            red_s[0] = mu;
            red_q[0] = rsqrtf(var + 1e-5f);
        }
        __syncthreads();
        const float mu   = red_s[0];
        const float rstd = red_q[0];

        #pragma unroll
        for (int tld = 0; tld < 8; ++tld) {
            const int jj = tid + tld * 256;
            sh[jj] = (g_h1[jj] - mu) * rstd * __ldg(ln_g + jj) + __ldg(ln_b + jj);
        }
        __syncthreads();

        const int g = b * 8 + warp;               // 832 W1 rows exactly
        const float4* W4 = reinterpret_cast<const float4*>(W1 + (size_t)g * H);
        float acc = 0.f;
        #pragma unroll
        for (int it = 0; it < 16; ++it) {
            float4 w  = __ldg(W4 + it * 32 + lane);
            float4 hv = sh4[it * 32 + lane];
            acc += dot4(w, hv);
        }
        acc = warp_red(acc);
        if (lane == 0)
            g_hid[g] = fmaxf(acc + __ldg(b1 + g), 0.0f);
    }

    // ============ completion; last block computes W2 + resets =============
    __syncthreads();
    if (tid == 0) { __threadfence(); s_tok = atomicAdd(&g_done, 1u); }
    __syncthreads();

    if (s_tok == GRID - 1) {
        __threadfence();
        for (int jo = warp; jo < NOUT; jo += 8) {
            const int k = c_pair_k[jo], p = c_pair_p[jo];
            const float* hid = g_hid + k * 64;
            const float* w2  = W2 + ((size_t)k * MAXO + p) * 64;
            float acc = hid[lane] * w2[lane] + hid[lane + 32] * w2[lane + 32];
            acc = warp_red(acc);
            if (lane == 0)
                out[OUT_HEAD + jo] = acc + b2[k * MAXO + p];
        }
        __syncthreads();
        if (tid == 0) {               // clean state for next graph replay
            *(volatile unsigned*)&g_bar1 = 0u;
            *(volatile unsigned*)&g_done = 0u;
            __threadfence();
        }
    }
}

// ---------------------------------------------------------------------------
extern "C" void kernel_launch(void* const* d_in, const int* in_sizes, int n_in,
                              void* d_out, int out_size)
{
    const float* lap        = (const float*)d_in[0];
    const int*   idx        = (const int*)  d_in[1];
    const float* h_s        = (const float*)d_in[2];
    const float* c_s        = (const float*)d_in[3];
    const float* emb_team   = (const float*)d_in[4];
    const float* emb_track  = (const float*)d_in[5];
    const float* emb_driver = (const float*)d_in[6];
    const float* emb_comp   = (const float*)d_in[7];
    const float* Wih0       = (const float*)d_in[8];
    const float* Whh0       = (const float*)d_in[9];
    const float* bih0       = (const float*)d_in[10];
    const float* bhh0       = (const float*)d_in[11];
    const float* Wih1       = (const float*)d_in[12];
    const float* Whh1       = (const float*)d_in[13];
    const float* bih1       = (const float*)d_in[14];
    const float* bhh1       = (const float*)d_in[15];
    const float* ln_g       = (const float*)d_in[16];
    const float* ln_b       = (const float*)d_in[17];
    const float* hW1        = (const float*)d_in[18];
    const float* hb1        = (const float*)d_in[19];
    const float* hW2        = (const float*)d_in[20];
    const float* hb2        = (const float*)d_in[21];
    float* out = (float*)d_out;

    k_all<<<GRID, TPB>>>(lap, idx, h_s, c_s, emb_team, emb_track, emb_driver,
                         emb_comp, Wih0, Whh0, bih0, bhh0, Wih1, Whh1, bih1,
                         bhh1, ln_g, ln_b, hW1, hb1, hW2, hb2, out);
}